// round 1
// baseline (speedup 1.0000x reference)
#include <cuda_runtime.h>

#define B_   1024
#define F_   1024
#define E_   256
#define L1_  16
#define L2C_ 8
#define L3C_ 32
#define NE3_ 128

// Routing scratch (static device memory — no allocations allowed).
__device__ int g_cnt2[L1_];
__device__ int g_rows2[L1_ * B_];
__device__ int g_cnt3[NE3_];
__device__ int g_rows3[NE3_ * B_];

__global__ void k_zero_counts() {
    int t = threadIdx.x;
    if (t < L1_)  g_cnt2[t] = 0;
    if (t < NE3_) g_cnt3[t] = 0;
}

// Unified expert kernel.
// LEVEL=1: dense, expert 0, rows = contiguous chunks (grid.x = 128 chunks of 8).
// LEVEL=2: grid.x = 16 experts, grid.y chunk slots (stride loop), input 0.6x+0.4y.
// LEVEL=3: grid.x = 128 experts, grid.y chunk slots, input x, no argmax.
template <int LEVEL, int LOUT>
__global__ void __launch_bounds__(256) k_expert(
    const float* __restrict__ x, const float* __restrict__ y,
    const float* __restrict__ W1, const float* __restrict__ gma,
    const float* __restrict__ bta, const float* __restrict__ W2,
    const float* __restrict__ b2, float* __restrict__ out)
{
    __shared__ __align__(16) float xs[8][F_];   // 32 KB: 8 input rows
    __shared__ __align__(16) float ht[8][E_];   // 8 KB: hidden tile
    __shared__ float lrow[8][LOUT];
    __shared__ float redm[8], redr[8];
    __shared__ int rowids[8];

    const int tid = threadIdx.x;
    const int e = (LEVEL == 1) ? 0 : blockIdx.x;
    const int n = (LEVEL == 1) ? B_ : ((LEVEL == 2) ? g_cnt2[e] : g_cnt3[e]);
    const int cstart = (LEVEL == 1) ? blockIdx.x : blockIdx.y;
    const int cstep  = (LEVEL == 1) ? (B_ / 8) : gridDim.y;

    const float* gma_e = gma + e * E_;
    const float* bta_e = bta + e * E_;
    const float* W2_e  = W2 + (size_t)e * E_ * LOUT;
    const float* b2_e  = b2 + e * LOUT;
    const int outoff = (LEVEL == 1) ? 0
                     : ((LEVEL == 2) ? B_ * L1_ : B_ * (L1_ + L2C_));

    for (int c = cstart; c * 8 < n; c += cstep) {
        // --- fetch row ids for this chunk ---
        if (tid < 8) {
            int rid = -1;
            int j = c * 8 + tid;
            if (j < n) {
                rid = (LEVEL == 1) ? j
                    : ((LEVEL == 2) ? g_rows2[e * B_ + j] : g_rows3[e * B_ + j]);
            }
            rowids[tid] = rid;
        }
        __syncthreads();

        // --- stage input rows in smem (float4, ft = 0.6x+0.4y for L2) ---
        for (int i = tid; i < 8 * (F_ / 4); i += 256) {
            int rr = i >> 8;          // F_/4 == 256
            int f4 = i & 255;
            int row = rowids[rr];
            float4 v = make_float4(0.f, 0.f, 0.f, 0.f);
            if (row >= 0) {
                float4 xv = reinterpret_cast<const float4*>(x)[row * (F_ / 4) + f4];
                if (LEVEL == 2) {
                    float4 yv = reinterpret_cast<const float4*>(y)[row * (F_ / 4) + f4];
                    v = make_float4(0.6f * xv.x + 0.4f * yv.x,
                                    0.6f * xv.y + 0.4f * yv.y,
                                    0.6f * xv.z + 0.4f * yv.z,
                                    0.6f * xv.w + 0.4f * yv.w);
                } else {
                    v = xv;
                }
            }
            reinterpret_cast<float4*>(&xs[rr][0])[f4] = v;
        }
        __syncthreads();

        // --- main GEMM: thread tid owns hidden column h = tid ---
        float acc[8];
        #pragma unroll
        for (int r = 0; r < 8; ++r) acc[r] = 0.f;

        const float* Wc = W1 + (size_t)e * F_ * E_ + tid;
        #pragma unroll 2
        for (int j = 0; j < F_ / 4; ++j) {
            float w0 = Wc[(4 * j + 0) * E_];
            float w1 = Wc[(4 * j + 1) * E_];
            float w2 = Wc[(4 * j + 2) * E_];
            float w3 = Wc[(4 * j + 3) * E_];
            #pragma unroll
            for (int r = 0; r < 8; ++r) {
                float4 xv = reinterpret_cast<const float4*>(&xs[r][0])[j];
                acc[r] = fmaf(xv.x, w0, acc[r]);
                acc[r] = fmaf(xv.y, w1, acc[r]);
                acc[r] = fmaf(xv.z, w2, acc[r]);
                acc[r] = fmaf(xv.w, w3, acc[r]);
            }
        }
        #pragma unroll
        for (int r = 0; r < 8; ++r) ht[r][tid] = acc[r];
        __syncthreads();

        // --- LayerNorm: warp w reduces row w ---
        {
            int w = tid >> 5, lane = tid & 31;
            float s = 0.f, ss = 0.f;
            #pragma unroll
            for (int k = lane; k < E_; k += 32) {
                float v = ht[w][k];
                s += v; ss += v * v;
            }
            #pragma unroll
            for (int o = 16; o > 0; o >>= 1) {
                s  += __shfl_xor_sync(0xffffffffu, s, o);
                ss += __shfl_xor_sync(0xffffffffu, ss, o);
            }
            if (lane == 0) {
                float m = s * (1.f / E_);
                float var = ss * (1.f / E_) - m * m;
                redm[w] = m;
                redr[w] = rsqrtf(var + 1e-5f);
            }
        }
        __syncthreads();

        // --- normalize + affine + ReLU ---
        {
            float gv = gma_e[tid], bv = bta_e[tid];
            #pragma unroll
            for (int r = 0; r < 8; ++r) {
                float v = (ht[r][tid] - redm[r]) * redr[r] * gv + bv;
                ht[r][tid] = fmaxf(v, 0.f);
            }
        }
        __syncthreads();

        // --- head GEMM: task (r, cc), 8*LOUT tasks ---
        if (tid < 8 * LOUT) {
            int r = tid / LOUT, cc = tid % LOUT;
            int row = rowids[r];
            if (row >= 0) {
                float s = b2_e[cc];
                #pragma unroll 4
                for (int k = 0; k < E_; ++k)
                    s = fmaf(ht[r][k], W2_e[k * LOUT + cc], s);
                out[outoff + row * LOUT + cc] = s;
                if (LEVEL != 3) lrow[r][cc] = s;
            }
        }

        // --- argmax + bucket push (levels 1, 2) ---
        if (LEVEL != 3) {
            __syncthreads();
            if (tid < 8) {
                int row = rowids[tid];
                if (row >= 0) {
                    float best = lrow[tid][0];
                    int bi = 0;
                    #pragma unroll
                    for (int cc = 1; cc < LOUT; ++cc) {
                        float v = lrow[tid][cc];
                        if (v > best) { best = v; bi = cc; }
                    }
                    if (LEVEL == 1) {
                        int pos = atomicAdd(&g_cnt2[bi], 1);
                        g_rows2[bi * B_ + pos] = row;
                    } else {
                        int ei = e * L2C_ + bi;
                        int pos = atomicAdd(&g_cnt3[ei], 1);
                        g_rows3[ei * B_ + pos] = row;
                    }
                }
            }
        }
        __syncthreads();   // protect smem before next chunk
    }
}

extern "C" void kernel_launch(void* const* d_in, const int* in_sizes, int n_in,
                              void* d_out, int out_size) {
    const float* x    = (const float*)d_in[0];
    const float* y    = (const float*)d_in[1];
    const float* l1W1 = (const float*)d_in[2];
    const float* l1g  = (const float*)d_in[3];
    const float* l1b  = (const float*)d_in[4];
    const float* l1W2 = (const float*)d_in[5];
    const float* l1b2 = (const float*)d_in[6];
    const float* l2W1 = (const float*)d_in[7];
    const float* l2g  = (const float*)d_in[8];
    const float* l2b  = (const float*)d_in[9];
    const float* l2W2 = (const float*)d_in[10];
    const float* l2b2 = (const float*)d_in[11];
    const float* l3W1 = (const float*)d_in[12];
    const float* l3g  = (const float*)d_in[13];
    const float* l3b  = (const float*)d_in[14];
    const float* l3W2 = (const float*)d_in[15];
    const float* l3b2 = (const float*)d_in[16];
    float* out = (float*)d_out;

    k_zero_counts<<<1, 256>>>();
    // Level 1: 128 chunks of 8 rows, dense.
    k_expert<1, L1_><<<dim3(128, 1), 256>>>(x, y, l1W1, l1g, l1b, l1W2, l1b2, out);
    // Level 2: 16 experts x 16 chunk slots (stride loop covers any skew).
    k_expert<2, L2C_><<<dim3(16, 16), 256>>>(x, y, l2W1, l2g, l2b, l2W2, l2b2, out);
    // Level 3: 128 experts x 4 chunk slots (stride loop covers any skew).
    k_expert<3, L3C_><<<dim3(128, 4), 256>>>(x, y, l3W1, l3g, l3b, l3W2, l3b2, out);
}

// round 2
// speedup vs baseline: 4.2645x; 4.2645x over previous
#include <cuda_runtime.h>

#define B_   1024
#define F_   1024
#define E_   256
#define L1_  16
#define L2C_ 8
#define L3C_ 32
#define NE3_ 128

// Dynamic smem layout (floats):
//   xs : [8][F_]            = 8192 floats (32 KB)
//   red: [8][8][64] float4  = 16384 floats (64 KB)  -- aliased by w2s after use
//   ht : [8][E_]            = 2048 floats (8 KB)
#define SM_XS   0
#define SM_RED  (8 * F_)
#define SM_HT   (SM_RED + 16384)
#define SMEM_SZ ((SM_HT + 8 * E_) * 4)

// Routing scratch (static device memory — no allocations allowed).
__device__ int g_cnt2[L1_];
__device__ int g_rows2[L1_ * B_];
__device__ int g_cnt3[NE3_];
__device__ int g_rows3[NE3_ * B_];

__global__ void k_zero_counts() {
    int t = threadIdx.x;
    if (t < L1_)  g_cnt2[t] = 0;
    if (t < NE3_) g_cnt3[t] = 0;
}

// Unified expert kernel, 512 threads.
// LEVEL=1: dense, expert 0, rows = contiguous chunks (grid.x = 128 chunks of 8).
// LEVEL=2: grid.x = 16 experts, grid.y chunk slots (stride loop), input 0.6x+0.4y.
// LEVEL=3: grid.x = 128 experts, grid.y chunk slots, input x, no argmax.
template <int LEVEL, int LOUT>
__global__ void __launch_bounds__(512, 1) k_expert(
    const float* __restrict__ x, const float* __restrict__ y,
    const float* __restrict__ W1, const float* __restrict__ gma,
    const float* __restrict__ bta, const float* __restrict__ W2,
    const float* __restrict__ b2, float* __restrict__ out)
{
    extern __shared__ float sm[];
    float*  xs  = sm + SM_XS;                  // [8][F_]
    float4* red = (float4*)(sm + SM_RED);      // [8 ks][8 r][64 cg]
    float*  w2s = sm + SM_RED;                 // alias: [E_][LOUT]
    float*  ht  = sm + SM_HT;                  // [8][E_]

    __shared__ float lrow[8][LOUT];
    __shared__ float redm[8], redr[8];
    __shared__ int rowids[8];

    const int tid = threadIdx.x;
    const int e = (LEVEL == 1) ? 0 : blockIdx.x;
    const int n = (LEVEL == 1) ? B_ : ((LEVEL == 2) ? g_cnt2[e] : g_cnt3[e]);
    const int cstart = (LEVEL == 1) ? blockIdx.x : blockIdx.y;
    const int cstep  = (LEVEL == 1) ? (B_ / 8) : gridDim.y;

    const float* gma_e = gma + e * E_;
    const float* bta_e = bta + e * E_;
    const float* W2_e  = W2 + (size_t)e * E_ * LOUT;
    const float* b2_e  = b2 + e * LOUT;
    const int outoff = (LEVEL == 1) ? 0
                     : ((LEVEL == 2) ? B_ * L1_ : B_ * (L1_ + L2C_));

    const int ks = tid >> 6;   // k-segment 0..7 (128 k each)
    const int cg = tid & 63;   // column group: owns cols 4cg..4cg+3

    for (int c = cstart; c * 8 < n; c += cstep) {
        // --- fetch row ids for this chunk ---
        if (tid < 8) {
            int rid = -1;
            int j = c * 8 + tid;
            if (j < n) {
                rid = (LEVEL == 1) ? j
                    : ((LEVEL == 2) ? g_rows2[e * B_ + j] : g_rows3[e * B_ + j]);
            }
            rowids[tid] = rid;
        }
        __syncthreads();

        // --- stage input rows in smem (float4, ft = 0.6x+0.4y for L2) ---
        for (int i = tid; i < 8 * (F_ / 4); i += 512) {
            int rr = i >> 8;          // F_/4 == 256
            int f4 = i & 255;
            int row = rowids[rr];
            float4 v = make_float4(0.f, 0.f, 0.f, 0.f);
            if (row >= 0) {
                float4 xv = reinterpret_cast<const float4*>(x)[row * (F_ / 4) + f4];
                if (LEVEL == 2) {
                    float4 yv = reinterpret_cast<const float4*>(y)[row * (F_ / 4) + f4];
                    v = make_float4(0.6f * xv.x + 0.4f * yv.x,
                                    0.6f * xv.y + 0.4f * yv.y,
                                    0.6f * xv.z + 0.4f * yv.z,
                                    0.6f * xv.w + 0.4f * yv.w);
                } else {
                    v = xv;
                }
            }
            reinterpret_cast<float4*>(&xs[rr * F_])[f4] = v;
        }
        __syncthreads();

        // --- main GEMM: thread (ks, cg) computes partial over k in
        //     [128ks, 128ks+128) for cols 4cg..4cg+3, all 8 rows ---
        float4 acc[8];
        #pragma unroll
        for (int r = 0; r < 8; ++r) acc[r] = make_float4(0.f, 0.f, 0.f, 0.f);

        const float* Wp = W1 + (size_t)e * F_ * E_ + (size_t)(ks * 128) * E_ + cg * 4;
        const float* xsk = xs + ks * 128;

        #pragma unroll 2
        for (int j4 = 0; j4 < 32; ++j4) {
            float4 xv[8];
            #pragma unroll
            for (int r = 0; r < 8; ++r)
                xv[r] = *reinterpret_cast<const float4*>(&xsk[r * F_ + j4 * 4]);
            #pragma unroll
            for (int jj = 0; jj < 4; ++jj) {
                float4 w = *reinterpret_cast<const float4*>(Wp + (size_t)(j4 * 4 + jj) * E_);
                #pragma unroll
                for (int r = 0; r < 8; ++r) {
                    float xvv = (jj == 0) ? xv[r].x : (jj == 1) ? xv[r].y
                              : (jj == 2) ? xv[r].z : xv[r].w;
                    acc[r].x = fmaf(xvv, w.x, acc[r].x);
                    acc[r].y = fmaf(xvv, w.y, acc[r].y);
                    acc[r].z = fmaf(xvv, w.z, acc[r].z);
                    acc[r].w = fmaf(xvv, w.w, acc[r].w);
                }
            }
        }
        #pragma unroll
        for (int r = 0; r < 8; ++r)
            red[(ks * 8 + r) * 64 + cg] = acc[r];
        __syncthreads();

        // --- cross-segment reduction: thread (r=tid>>6, cg=tid&63) ---
        {
            int rr = tid >> 6;
            float4 s = red[(0 * 8 + rr) * 64 + cg];
            #pragma unroll
            for (int k = 1; k < 8; ++k) {
                float4 p = red[(k * 8 + rr) * 64 + cg];
                s.x += p.x; s.y += p.y; s.z += p.z; s.w += p.w;
            }
            reinterpret_cast<float4*>(&ht[rr * E_])[cg] = s;
        }
        __syncthreads();

        // --- LayerNorm stats: warp w (< 8) reduces row w ---
        if (tid < 256) {
            int w = tid >> 5, lane = tid & 31;
            float s = 0.f, ss = 0.f;
            #pragma unroll
            for (int k = lane; k < E_; k += 32) {
                float v = ht[w * E_ + k];
                s += v; ss += v * v;
            }
            #pragma unroll
            for (int o = 16; o > 0; o >>= 1) {
                s  += __shfl_xor_sync(0xffffffffu, s, o);
                ss += __shfl_xor_sync(0xffffffffu, ss, o);
            }
            if (lane == 0) {
                float m = s * (1.f / E_);
                float var = ss * (1.f / E_) - m * m;
                redm[w] = m;
                redr[w] = rsqrtf(var + 1e-5f);
            }
        }
        __syncthreads();

        // --- normalize + affine + ReLU; concurrently stage W2 (alias over red) ---
        {
            int cc = tid & 255;
            int rbase = (tid >> 8) * 4;
            float gv = gma_e[cc], bv = bta_e[cc];
            #pragma unroll
            for (int rr = 0; rr < 4; ++rr) {
                int r = rbase + rr;
                float v = (ht[r * E_ + cc] - redm[r]) * redr[r] * gv + bv;
                ht[r * E_ + cc] = fmaxf(v, 0.f);
            }
            for (int i = tid; i < E_ * LOUT; i += 512)
                w2s[i] = W2_e[i];
        }
        __syncthreads();

        // --- head GEMM from smem: task (r, cc) ---
        if (tid < 8 * LOUT) {
            int r = tid / LOUT, cc = tid % LOUT;
            int row = rowids[r];
            if (row >= 0) {
                float s = b2_e[cc];
                #pragma unroll 8
                for (int k = 0; k < E_; ++k)
                    s = fmaf(ht[r * E_ + k], w2s[k * LOUT + cc], s);
                out[outoff + row * LOUT + cc] = s;
                if (LEVEL != 3) lrow[r][cc] = s;
            }
        }

        // --- argmax + bucket push (levels 1, 2) ---
        if (LEVEL != 3) {
            __syncthreads();
            if (tid < 8) {
                int row = rowids[tid];
                if (row >= 0) {
                    float best = lrow[tid][0];
                    int bi = 0;
                    #pragma unroll
                    for (int cc = 1; cc < LOUT; ++cc) {
                        float v = lrow[tid][cc];
                        if (v > best) { best = v; bi = cc; }
                    }
                    if (LEVEL == 1) {
                        int pos = atomicAdd(&g_cnt2[bi], 1);
                        g_rows2[bi * B_ + pos] = row;
                    } else {
                        int ei = e * L2C_ + bi;
                        int pos = atomicAdd(&g_cnt3[ei], 1);
                        g_rows3[ei * B_ + pos] = row;
                    }
                }
            }
        }
        __syncthreads();   // protect smem before next chunk
    }
}

extern "C" void kernel_launch(void* const* d_in, const int* in_sizes, int n_in,
                              void* d_out, int out_size) {
    const float* x    = (const float*)d_in[0];
    const float* y    = (const float*)d_in[1];
    const float* l1W1 = (const float*)d_in[2];
    const float* l1g  = (const float*)d_in[3];
    const float* l1b  = (const float*)d_in[4];
    const float* l1W2 = (const float*)d_in[5];
    const float* l1b2 = (const float*)d_in[6];
    const float* l2W1 = (const float*)d_in[7];
    const float* l2g  = (const float*)d_in[8];
    const float* l2b  = (const float*)d_in[9];
    const float* l2W2 = (const float*)d_in[10];
    const float* l2b2 = (const float*)d_in[11];
    const float* l3W1 = (const float*)d_in[12];
    const float* l3g  = (const float*)d_in[13];
    const float* l3b  = (const float*)d_in[14];
    const float* l3W2 = (const float*)d_in[15];
    const float* l3b2 = (const float*)d_in[16];
    float* out = (float*)d_out;

    // Allow >48KB dynamic smem (idempotent; safe under graph capture).
    cudaFuncSetAttribute((const void*)k_expert<1, L1_>,
                         cudaFuncAttributeMaxDynamicSharedMemorySize, SMEM_SZ);
    cudaFuncSetAttribute((const void*)k_expert<2, L2C_>,
                         cudaFuncAttributeMaxDynamicSharedMemorySize, SMEM_SZ);
    cudaFuncSetAttribute((const void*)k_expert<3, L3C_>,
                         cudaFuncAttributeMaxDynamicSharedMemorySize, SMEM_SZ);

    k_zero_counts<<<1, 256>>>();
    // Level 1: 128 chunks of 8 rows, dense.
    k_expert<1, L1_><<<dim3(128, 1), 512, SMEM_SZ>>>(x, y, l1W1, l1g, l1b, l1W2, l1b2, out);
    // Level 2: 16 experts x 16 chunk slots (stride loop covers any skew).
    k_expert<2, L2C_><<<dim3(16, 16), 512, SMEM_SZ>>>(x, y, l2W1, l2g, l2b, l2W2, l2b2, out);
    // Level 3: 128 experts x 4 chunk slots (stride loop covers any skew).
    k_expert<3, L3C_><<<dim3(128, 4), 512, SMEM_SZ>>>(x, y, l3W1, l3g, l3b, l3W2, l3b2, out);
}